// round 2
// baseline (speedup 1.0000x reference)
#include <cuda_runtime.h>

#define THRESHOLD 0.5f
#define B 256
#define HW 49          // 7*7
#define C_INTERM 1000
#define C_VGG 512

// Scratch: thresholded CAM value per (batch, spatial) cell. 12544 floats.
__device__ float g_tvals[B * HW];

// ---------------------------------------------------------------------------
// Kernel 1: per-batch argmax over branchA_end[b, 0:1000] (first-index wins),
// then gather interm[b, hw, idx] for hw in [0,49), threshold, store scratch.
// One block (128 threads) per batch.
// ---------------------------------------------------------------------------
__global__ __launch_bounds__(128) void argmax_gather_kernel(
    const float* __restrict__ branchA,   // [B, 1000]
    const float* __restrict__ interm)    // [B, 49, 1000]
{
    const int b   = blockIdx.x;
    const int tid = threadIdx.x;

    const float* row = branchA + (size_t)b * C_INTERM;

    // Each thread scans a strided slice; first-index-wins ties.
    float best_v = -__FLT_MAX__;
    int   best_i = C_INTERM;  // sentinel larger than any real index
    #pragma unroll
    for (int i = tid; i < C_INTERM; i += 128) {
        float v = row[i];
        if (v > best_v || (v == best_v && i < best_i)) {
            best_v = v;
            best_i = i;
        }
    }

    __shared__ float s_v[128];
    __shared__ int   s_i[128];
    s_v[tid] = best_v;
    s_i[tid] = best_i;
    __syncthreads();

    // Tree reduction, first-index-wins on equal values.
    for (int off = 64; off > 0; off >>= 1) {
        if (tid < off) {
            float ov = s_v[tid + off];
            int   oi = s_i[tid + off];
            if (ov > s_v[tid] || (ov == s_v[tid] && oi < s_i[tid])) {
                s_v[tid] = ov;
                s_i[tid] = oi;
            }
        }
        __syncthreads();
    }

    const int idx = s_i[0];

    // Gather + threshold for the 49 spatial cells of this batch.
    if (tid < HW) {
        float a = __ldg(interm + ((size_t)b * HW + tid) * C_INTERM + idx);
        g_tvals[b * HW + tid] = (a > THRESHOLD) ? a : 0.0f;
    }
}

// ---------------------------------------------------------------------------
// Kernel 2: out[b,hw,c] = vgg_end[b,hw,c] - t[b,hw], float4-vectorized,
// 8 independent float4 loads per thread (MLP=8) to hide DRAM latency.
// 2048 float4 per block * 784 blocks = 1,605,632 float4 exactly.
// ---------------------------------------------------------------------------
#define VEC_PER_THREAD 8

__global__ __launch_bounds__(256) void subtract_kernel(
    const float4* __restrict__ vgg,   // [B*HW*512/4]
    float4* __restrict__ out)
{
    const int base = blockIdx.x * (256 * VEC_PER_THREAD) + threadIdx.x;

    // Front-batch all global loads: 8 independent LDG.128 in flight.
    float4 v[VEC_PER_THREAD];
    float  t[VEC_PER_THREAD];
    #pragma unroll
    for (int k = 0; k < VEC_PER_THREAD; k++) {
        const int i = base + k * 256;
        v[k] = vgg[i];
        t[k] = g_tvals[i >> 7];   // L1/L2-resident 50KB table
    }

    #pragma unroll
    for (int k = 0; k < VEC_PER_THREAD; k++) {
        const int i = base + k * 256;
        float4 r = v[k];
        r.x -= t[k]; r.y -= t[k]; r.z -= t[k]; r.w -= t[k];
        out[i] = r;
    }
}

extern "C" void kernel_launch(void* const* d_in, const int* in_sizes, int n_in,
                              void* d_out, int out_size) {
    const float* vgg_end = (const float*)d_in[0];  // [256,7,7,512]
    const float* interm  = (const float*)d_in[1];  // [256,7,7,1000]
    const float* branchA = (const float*)d_in[2];  // [256,1000]
    float*       out     = (float*)d_out;

    argmax_gather_kernel<<<B, 128>>>(branchA, interm);

    const int n4     = B * HW * C_VGG / 4;              // 1,605,632
    const int blocks = n4 / (256 * VEC_PER_THREAD);     // 784 exact
    subtract_kernel<<<blocks, 256>>>((const float4*)vgg_end, (float4*)out);
}

// round 3
// speedup vs baseline: 1.1599x; 1.1599x over previous
#include <cuda_runtime.h>
#include <float.h>

#define THRESHOLD 0.5f
#define B 256
#define HW 49            // 7*7
#define C_INTERM 1000
#define C_VGG 512
#define F4_PER_BATCH (HW * C_VGG / 4)       // 6272
#define PARTS 4
#define F4_PER_PART (F4_PER_BATCH / PARTS)  // 1568 = 6*256 + 32

// ---------------------------------------------------------------------------
// Fused kernel: 4 blocks per batch. Each block:
//   Phase A: argmax over branchA[b,0:1000] (first-index-wins),
//            gather interm[b,hw,idx] for all 49 cells -> shared (thresholded).
//   Phase B: stream its quarter of vgg_end: out = vgg - t[cell].
// ---------------------------------------------------------------------------
__global__ __launch_bounds__(256) void fused_kernel(
    const float*  __restrict__ branchA,  // [B, 1000]
    const float*  __restrict__ interm,   // [B, 49, 1000]
    const float4* __restrict__ vgg,      // [B*49*512/4]
    float4*       __restrict__ out)
{
    const int b    = blockIdx.x >> 2;
    const int part = blockIdx.x & 3;
    const int tid  = threadIdx.x;

    // ---------------- Phase A: block argmax (first-index-wins) -------------
    const float* row = branchA + (size_t)b * C_INTERM;

    float best_v = -FLT_MAX;
    int   best_i = C_INTERM;
    #pragma unroll
    for (int k = 0; k < 4; k++) {
        const int i = tid + k * 256;
        if (i < C_INTERM) {
            float v = __ldg(row + i);
            if (v > best_v || (v == best_v && i < best_i)) { best_v = v; best_i = i; }
        }
    }

    __shared__ float s_v[256];
    __shared__ int   s_i[256];
    __shared__ float s_t[HW];

    s_v[tid] = best_v;
    s_i[tid] = best_i;
    __syncthreads();

    #pragma unroll
    for (int off = 128; off > 0; off >>= 1) {
        if (tid < off) {
            float ov = s_v[tid + off];
            int   oi = s_i[tid + off];
            if (ov > s_v[tid] || (ov == s_v[tid] && oi < s_i[tid])) {
                s_v[tid] = ov;
                s_i[tid] = oi;
            }
        }
        __syncthreads();
    }

    const int idx = s_i[0];

    // Gather + threshold the 49 CAM values for this batch.
    if (tid < HW) {
        float a = __ldg(interm + ((size_t)b * HW + tid) * C_INTERM + idx);
        s_t[tid] = (a > THRESHOLD) ? a : 0.0f;
    }
    __syncthreads();

    // ---------------- Phase B: stream this block's quarter -----------------
    // Covers float4 indices [part*1568, part*1568+1568) within the batch.
    const int loc0  = part * F4_PER_PART + tid;           // local f4 index in batch
    const int base4 = b * F4_PER_BATCH + loc0;            // global f4 index

    // 6 full strides of 256, front-batched loads for MLP.
    float4 v[6];
    float  t[6];
    #pragma unroll
    for (int k = 0; k < 6; k++) {
        v[k] = __ldcs(&vgg[base4 + k * 256]);
        t[k] = s_t[(loc0 + k * 256) >> 7];     // 128 f4 per cell
    }
    #pragma unroll
    for (int k = 0; k < 6; k++) {
        float4 r = v[k];
        const float tv = t[k];
        r.x -= tv; r.y -= tv; r.z -= tv; r.w -= tv;
        __stcs(&out[base4 + k * 256], r);
    }

    // Tail: 1568 - 6*256 = 32 elements.
    if (tid < 32) {
        const int loc = loc0 + 6 * 256;
        const int gi  = base4 + 6 * 256;
        float4 r = __ldcs(&vgg[gi]);
        const float tv = s_t[loc >> 7];
        r.x -= tv; r.y -= tv; r.z -= tv; r.w -= tv;
        __stcs(&out[gi], r);
    }
}

extern "C" void kernel_launch(void* const* d_in, const int* in_sizes, int n_in,
                              void* d_out, int out_size) {
    const float* vgg_end = (const float*)d_in[0];  // [256,7,7,512]
    const float* interm  = (const float*)d_in[1];  // [256,7,7,1000]
    const float* branchA = (const float*)d_in[2];  // [256,1000]
    float*       out     = (float*)d_out;

    fused_kernel<<<B * PARTS, 256>>>(branchA, interm,
                                     (const float4*)vgg_end, (float4*)out);
}

// round 4
// speedup vs baseline: 1.1633x; 1.0029x over previous
#include <cuda_runtime.h>
#include <float.h>

#define THRESHOLD 0.5f
#define B 256
#define HW 49            // 7*7
#define C_INTERM 1000
#define C_VGG 512
#define F4_PER_BATCH (HW * C_VGG / 4)       // 6272
#define PARTS 4
#define F4_PER_PART (F4_PER_BATCH / PARTS)  // 1568 = 6*256 + 32

// ---------------------------------------------------------------------------
// Fused kernel, 4 blocks per batch, prologue hidden behind streaming loads:
//   Phase 0: front-issue ALL vgg loads for this block (independent of argmax)
//   Phase A: argmax over branchA[b,:] (first-index-wins, shuffle reduction),
//            gather interm[b,hw,idx] -> shared (thresholded)
//   Phase B: subtract + streaming store
// ---------------------------------------------------------------------------
__global__ __launch_bounds__(256) void fused_kernel(
    const float*  __restrict__ branchA,  // [B, 1000]
    const float*  __restrict__ interm,   // [B, 49, 1000]
    const float4* __restrict__ vgg,      // [B*49*512/4]
    float4*       __restrict__ out)
{
    const int b    = blockIdx.x >> 2;
    const int part = blockIdx.x & 3;
    const int tid  = threadIdx.x;
    const int lane = tid & 31;
    const int wid  = tid >> 5;

    // ---------------- Phase 0: front-issue streaming loads -----------------
    const int loc0  = part * F4_PER_PART + tid;   // local f4 index in batch
    const int base4 = b * F4_PER_BATCH + loc0;    // global f4 index

    float4 v[6];
    #pragma unroll
    for (int k = 0; k < 6; k++)
        v[k] = __ldcs(&vgg[base4 + k * 256]);

    float4 vt;                                    // tail: 32 extra f4 per part
    if (tid < 32)
        vt = __ldcs(&vgg[base4 + 6 * 256]);

    // ---------------- Phase A: argmax (first-index-wins) -------------------
    const float* row = branchA + (size_t)b * C_INTERM;

    float best_v = -FLT_MAX;
    int   best_i = C_INTERM;
    #pragma unroll
    for (int k = 0; k < 4; k++) {
        const int i = tid + k * 256;
        if (i < C_INTERM) {
            float x = __ldg(row + i);
            if (x > best_v || (x == best_v && i < best_i)) { best_v = x; best_i = i; }
        }
    }

    // Warp butterfly reduction on (v, i): lexicographic max (v desc, i asc).
    #pragma unroll
    for (int off = 16; off > 0; off >>= 1) {
        float ov = __shfl_xor_sync(0xFFFFFFFFu, best_v, off);
        int   oi = __shfl_xor_sync(0xFFFFFFFFu, best_i, off);
        if (ov > best_v || (ov == best_v && oi < best_i)) { best_v = ov; best_i = oi; }
    }

    __shared__ float s_wv[8];
    __shared__ int   s_wi[8];
    __shared__ int   s_idx;
    __shared__ float s_t[HW];

    if (lane == 0) { s_wv[wid] = best_v; s_wi[wid] = best_i; }
    __syncthreads();

    if (wid == 0) {
        float fv = (lane < 8) ? s_wv[lane] : -FLT_MAX;
        int   fi = (lane < 8) ? s_wi[lane] : C_INTERM;
        #pragma unroll
        for (int off = 4; off > 0; off >>= 1) {
            float ov = __shfl_xor_sync(0xFFFFFFFFu, fv, off);
            int   oi = __shfl_xor_sync(0xFFFFFFFFu, fi, off);
            if (ov > fv || (ov == fv && oi < fi)) { fv = ov; fi = oi; }
        }
        if (lane == 0) s_idx = fi;
    }
    __syncthreads();

    const int idx = s_idx;

    // Gather + threshold the 49 CAM values for this batch.
    if (tid < HW) {
        float a = __ldg(interm + ((size_t)b * HW + tid) * C_INTERM + idx);
        s_t[tid] = (a > THRESHOLD) ? a : 0.0f;
    }
    __syncthreads();

    // ---------------- Phase B: subtract + streaming store ------------------
    #pragma unroll
    for (int k = 0; k < 6; k++) {
        const float tv = s_t[(loc0 + k * 256) >> 7];   // 128 f4 per cell
        float4 r = v[k];
        r.x -= tv; r.y -= tv; r.z -= tv; r.w -= tv;
        __stcs(&out[base4 + k * 256], r);
    }

    if (tid < 32) {
        const float tv = s_t[(loc0 + 6 * 256) >> 7];
        float4 r = vt;
        r.x -= tv; r.y -= tv; r.z -= tv; r.w -= tv;
        __stcs(&out[base4 + 6 * 256], r);
    }
}

extern "C" void kernel_launch(void* const* d_in, const int* in_sizes, int n_in,
                              void* d_out, int out_size) {
    const float* vgg_end = (const float*)d_in[0];  // [256,7,7,512]
    const float* interm  = (const float*)d_in[1];  // [256,7,7,1000]
    const float* branchA = (const float*)d_in[2];  // [256,1000]
    float*       out     = (float*)d_out;

    fused_kernel<<<B * PARTS, 256>>>(branchA, interm,
                                     (const float4*)vgg_end, (float4*)out);
}